// round 7
// baseline (speedup 1.0000x reference)
#include <cuda_runtime.h>
#include <cuda_bf16.h>
#include <cstdint>

// ===========================================================================
// BiMamba via mma.sync bf16 hi/lo split GEMMs (3-product), pre-split operands,
// 3-stage cp.async pipeline (1 sync/stage), dual-direction launches.
// B=2, L=1024, D_MODEL=1024, D_INNER=2048, DT_RANK=64, D_STATE=16
// ===========================================================================

#define BSZ     2
#define SEQ     1024
#define DMODEL  1024
#define DINNER  2048
#define DTRANK  64
#define DSTATE  16
#define TOK     (BSZ*SEQ)

#define PLANE_XZ   ((size_t)TOK * (2*DINNER))
#define PLANE_E    ((size_t)TOK * DINNER)
#define PLANE_DBL  ((size_t)TOK * 96)

// fp32 intermediates
__device__ float g_xz[2][PLANE_XZ];     // xi | z per direction
__device__ float g_xc[2][PLANE_E];      // conv+silu output
__device__ float g_dbl[2][PLANE_DBL];   // dt(64) | B(16) | C(16)
__device__ float g_delta[2][PLANE_E];   // softplus(dt@dt_w + b)

// bf16 hi/lo split operands (packed rows: [hi(K) | lo(K)])
__device__ __nv_bfloat16 g_xbf [(size_t)TOK * 2*DMODEL];
__device__ __nv_bfloat16 g_wbf [2][(size_t)2*DINNER * 2*DMODEL];
__device__ __nv_bfloat16 g_wdt [2][(size_t)DINNER * 2*DTRANK];
__device__ __nv_bfloat16 g_wop [2][(size_t)DMODEL * 2*DINNER];
__device__ __nv_bfloat16 g_wmg [(size_t)DMODEL * 2*(2*DMODEL)];
__device__ __nv_bfloat16 g_dtbf[2][(size_t)TOK * 2*DTRANK];
__device__ __nv_bfloat16 g_ybf [2][(size_t)TOK * 2*DINNER];
__device__ __nv_bfloat16 g_ocat[(size_t)TOK * 2*(2*DMODEL)];

// ---------------------------------------------------------------------------
// asm helpers
// ---------------------------------------------------------------------------
__device__ __forceinline__ void ldsm_x4(uint32_t* r, uint32_t addr) {
    asm volatile("ldmatrix.sync.aligned.m8n8.x4.shared.b16 {%0,%1,%2,%3}, [%4];"
        : "=r"(r[0]), "=r"(r[1]), "=r"(r[2]), "=r"(r[3]) : "r"(addr));
}
__device__ __forceinline__ void mma16816(float* c, const uint32_t* a, const uint32_t* b) {
    asm volatile(
        "mma.sync.aligned.m16n8k16.row.col.f32.bf16.bf16.f32 "
        "{%0,%1,%2,%3}, {%4,%5,%6,%7}, {%8,%9}, {%0,%1,%2,%3};"
        : "+f"(c[0]), "+f"(c[1]), "+f"(c[2]), "+f"(c[3])
        : "r"(a[0]), "r"(a[1]), "r"(a[2]), "r"(a[3]), "r"(b[0]), "r"(b[1]));
}
#define CP_ASYNC16(dst, src) \
    asm volatile("cp.async.cg.shared.global [%0], [%1], 16;" :: "r"(dst), "l"(src))
#define CP_COMMIT() asm volatile("cp.async.commit_group;" ::: "memory")
#define CP_WAIT1()  asm volatile("cp.async.wait_group 1;" ::: "memory")
#define CP_WAIT0()  asm volatile("cp.async.wait_group 0;" ::: "memory")

// ---------------------------------------------------------------------------
// Main GEMM: 128x128 tile, virtual K' = 3K (AhBh, AhBl, AlBh), BK=64 chunks,
// 3-stage cp.async ring (one __syncthreads per stage), 8 warps (2x4).
// Dual-direction via blockIdx.z pointer sets; runtime flipa/flipc.
// ---------------------------------------------------------------------------
#define GSMEM (3*32768)

template<bool SOFTPLUS, bool OUTBF>
__global__ __launch_bounds__(256)
void gemm_bf16s(const __nv_bfloat16* __restrict__ A0, const __nv_bfloat16* __restrict__ A1,
                const __nv_bfloat16* __restrict__ B0, const __nv_bfloat16* __restrict__ B1,
                float* C0, float* C1, int ldc,
                __nv_bfloat16* Cb0, __nv_bfloat16* Cb1, int ldcb, int koffb,
                int K, const float* bias0, const float* bias1,
                int flipa0, int flipa1, int flipc0, int flipc1)
{
    extern __shared__ __align__(128) char smem_raw[];
    const uint32_t sbase = (uint32_t)__cvta_generic_to_shared(smem_raw);

    const int z = blockIdx.z;
    const __nv_bfloat16* A = z ? A1 : A0;
    const __nv_bfloat16* B = z ? B1 : B0;
    float* C = z ? C1 : C0;
    __nv_bfloat16* Cb = z ? Cb1 : Cb0;
    const float* bias = z ? bias1 : bias0;
    const int flipa = z ? flipa1 : flipa0;
    const int flipc = z ? flipc1 : flipc0;

    const int tid = threadIdx.x;
    const int wid = tid >> 5;
    const int lid = tid & 31;
    const int bm = blockIdx.y * 128;
    const int bn = blockIdx.x * 128;

    const int wm = wid >> 2;
    const int wn = wid & 3;
    const int mbase = wm * 64;
    const int nbase = wn * 32;

    const int qrow = lid & 15;          // ldmatrix x4 row-within-16
    const int qc16 = lid >> 4;          // 8-elem chunk select

    const int lda2 = 2 * K;
    const int nk = K >> 6;
    const int nv = 3 * nk;

    float acc[4][4][4];
#pragma unroll
    for (int f = 0; f < 4; f++)
#pragma unroll
        for (int g = 0; g < 4; g++)
#pragma unroll
            for (int e = 0; e < 4; e++) acc[f][g][e] = 0.f;

    auto sA = [&](int st) -> uint32_t { return sbase + (uint32_t)st * 32768u; };
    auto sB = [&](int st) -> uint32_t { return sbase + (uint32_t)st * 32768u + 16384u; };

    auto load_stage = [&](int v, int st) {
        int aoff, boff;
        if (v < nk)            { aoff = v << 6;                boff = v << 6; }
        else if (v < 2 * nk)   { aoff = (v - nk) << 6;         boff = K + ((v - nk) << 6); }
        else                   { aoff = K + ((v - 2*nk) << 6); boff = (v - 2*nk) << 6; }
        uint32_t da = sA(st), db = sB(st);
#pragma unroll
        for (int i = 0; i < 4; i++) {
            int ch  = tid + (i << 8);
            int r   = ch >> 3;
            int c16 = ch & 7;
            uint32_t sw = (uint32_t)((c16 ^ (r & 7)) << 4) + (uint32_t)(r << 7);
            int gm = bm + r;
            int am = flipa ? (gm ^ (SEQ-1)) : gm;
            CP_ASYNC16(da + sw, A + (size_t)am * lda2 + aoff + (c16 << 3));
            CP_ASYNC16(db + sw, B + (size_t)(bn + r) * lda2 + boff + (c16 << 3));
        }
    };

    auto compute_stage = [&](int st) {
        uint32_t sa = sA(st), sb = sB(st);
#pragma unroll
        for (int s = 0; s < 4; s++) {
            // B: 2 x ldmatrix.x4 covering 32 rows x 16 cols
            uint32_t bq[2][4];
#pragma unroll
            for (int g2 = 0; g2 < 2; g2++) {
                int r = nbase + g2*16 + qrow;
                int c = (s << 1) + qc16;
                ldsm_x4(bq[g2], sb + (uint32_t)(r << 7) + (uint32_t)((c ^ (r & 7)) << 4));
            }
#pragma unroll
            for (int f = 0; f < 4; f++) {
                int r = mbase + f*16 + qrow;
                int c = (s << 1) + qc16;
                uint32_t afr[4];
                ldsm_x4(afr, sa + (uint32_t)(r << 7) + (uint32_t)((c ^ (r & 7)) << 4));
#pragma unroll
                for (int g = 0; g < 4; g++) {
                    uint32_t bfr[2] = { bq[g >> 1][g & 1], bq[g >> 1][(g & 1) + 2] };
                    mma16816(acc[f][g], afr, bfr);
                }
            }
        }
    };

    load_stage(0, 0); CP_COMMIT();
    if (nv > 1) { load_stage(1, 1); CP_COMMIT(); }

    for (int v = 0; v < nv; v++) {
        int st = v % 3;
        if (v < nv - 1) CP_WAIT1(); else CP_WAIT0();
        __syncthreads();
        compute_stage(st);
        int vn = v + 2;
        if (vn < nv) { load_stage(vn, vn % 3); CP_COMMIT(); }
    }

    // ---- epilogue ----
    const int crow = lid >> 2;
    const int ccol = (lid & 3) * 2;
#pragma unroll
    for (int f = 0; f < 4; f++) {
        int m0 = bm + mbase + f*16 + crow;
        int m1 = m0 + 8;
        int gm0 = flipc ? (m0 ^ (SEQ-1)) : m0;
        int gm1 = flipc ? (m1 ^ (SEQ-1)) : m1;
#pragma unroll
        for (int g = 0; g < 4; g++) {
            int n = bn + nbase + g*8 + ccol;
            float v0 = acc[f][g][0], v1 = acc[f][g][1];
            float v2 = acc[f][g][2], v3 = acc[f][g][3];
            if (SOFTPLUS) {
                float b0 = bias[n], b1 = bias[n+1];
                float x0 = v0 + b0, x1 = v1 + b1, x2 = v2 + b0, x3 = v3 + b1;
                v0 = (x0 > 20.f) ? x0 : log1pf(__expf(x0));
                v1 = (x1 > 20.f) ? x1 : log1pf(__expf(x1));
                v2 = (x2 > 20.f) ? x2 : log1pf(__expf(x2));
                v3 = (x3 > 20.f) ? x3 : log1pf(__expf(x3));
            }
            if (OUTBF) {
                __nv_bfloat16 h0 = __float2bfloat16(v0);
                __nv_bfloat16 h1 = __float2bfloat16(v1);
                __nv_bfloat16 h2 = __float2bfloat16(v2);
                __nv_bfloat16 h3 = __float2bfloat16(v3);
                __nv_bfloat16 l0 = __float2bfloat16(v0 - __bfloat162float(h0));
                __nv_bfloat16 l1 = __float2bfloat16(v1 - __bfloat162float(h1));
                __nv_bfloat16 l2 = __float2bfloat16(v2 - __bfloat162float(h2));
                __nv_bfloat16 l3 = __float2bfloat16(v3 - __bfloat162float(h3));
                *reinterpret_cast<__nv_bfloat162*>(Cb + (size_t)gm0*ldcb + n)         = __halves2bfloat162(h0, h1);
                *reinterpret_cast<__nv_bfloat162*>(Cb + (size_t)gm0*ldcb + koffb + n) = __halves2bfloat162(l0, l1);
                *reinterpret_cast<__nv_bfloat162*>(Cb + (size_t)gm1*ldcb + n)         = __halves2bfloat162(h2, h3);
                *reinterpret_cast<__nv_bfloat162*>(Cb + (size_t)gm1*ldcb + koffb + n) = __halves2bfloat162(l2, l3);
            } else {
                *reinterpret_cast<float2*>(C + (size_t)gm0*ldc + n) = make_float2(v0, v1);
                *reinterpret_cast<float2*>(C + (size_t)gm1*ldc + n) = make_float2(v2, v3);
            }
        }
    }
}

// ---------------------------------------------------------------------------
// fp32 -> [hi(K)|lo(K)] bf16 split converter
// ---------------------------------------------------------------------------
__global__ void cvt_split(const float* __restrict__ in, __nv_bfloat16* __restrict__ out, int K)
{
    int idx = (blockIdx.x * blockDim.x + threadIdx.x) << 2;
    int row = idx / K;
    int col = idx - row * K;
    float4 v = *reinterpret_cast<const float4*>(in + idx);
    __nv_bfloat16 h0 = __float2bfloat16(v.x), h1 = __float2bfloat16(v.y);
    __nv_bfloat16 h2 = __float2bfloat16(v.z), h3 = __float2bfloat16(v.w);
    __nv_bfloat16 l0 = __float2bfloat16(v.x - __bfloat162float(h0));
    __nv_bfloat16 l1 = __float2bfloat16(v.y - __bfloat162float(h1));
    __nv_bfloat16 l2 = __float2bfloat16(v.z - __bfloat162float(h2));
    __nv_bfloat16 l3 = __float2bfloat16(v.w - __bfloat162float(h3));
    size_t o = (size_t)row * 2 * K + col;
    *reinterpret_cast<__nv_bfloat162*>(out + o)         = __halves2bfloat162(h0, h1);
    *reinterpret_cast<__nv_bfloat162*>(out + o + 2)     = __halves2bfloat162(h2, h3);
    *reinterpret_cast<__nv_bfloat162*>(out + o + K)     = __halves2bfloat162(l0, l1);
    *reinterpret_cast<__nv_bfloat162*>(out + o + K + 2) = __halves2bfloat162(l2, l3);
}

// dbl (stride 96, cols 0..63) -> packed 2048 x 128 split; both dirs (grid.y)
__global__ void cvt_dt(const float* __restrict__ in0, __nv_bfloat16* __restrict__ out0,
                       const float* __restrict__ in1, __nv_bfloat16* __restrict__ out1)
{
    const float* in = blockIdx.y ? in1 : in0;
    __nv_bfloat16* out = blockIdx.y ? out1 : out0;
    int idx = (blockIdx.x * blockDim.x + threadIdx.x) << 2;
    int row = idx >> 6;
    int col = idx & 63;
    float4 v = *reinterpret_cast<const float4*>(in + (size_t)row * 96 + col);
    __nv_bfloat16 h0 = __float2bfloat16(v.x), h1 = __float2bfloat16(v.y);
    __nv_bfloat16 h2 = __float2bfloat16(v.z), h3 = __float2bfloat16(v.w);
    __nv_bfloat16 l0 = __float2bfloat16(v.x - __bfloat162float(h0));
    __nv_bfloat16 l1 = __float2bfloat16(v.y - __bfloat162float(h1));
    __nv_bfloat16 l2 = __float2bfloat16(v.z - __bfloat162float(h2));
    __nv_bfloat16 l3 = __float2bfloat16(v.w - __bfloat162float(h3));
    size_t o = (size_t)row * 128 + col;
    *reinterpret_cast<__nv_bfloat162*>(out + o)          = __halves2bfloat162(h0, h1);
    *reinterpret_cast<__nv_bfloat162*>(out + o + 2)      = __halves2bfloat162(h2, h3);
    *reinterpret_cast<__nv_bfloat162*>(out + o + 64)     = __halves2bfloat162(l0, l1);
    *reinterpret_cast<__nv_bfloat162*>(out + o + 64 + 2) = __halves2bfloat162(l2, l3);
}

// ---------------------------------------------------------------------------
// Small split-K fp32 GEMM with atomicAdd epilogue (x_proj), both dirs (grid.z)
// ---------------------------------------------------------------------------
template<int BM,int BN,int BK,int TM,int TN>
__global__ __launch_bounds__((BM/TM)*(BN/TN))
void gemm_nt_atomic(const float* __restrict__ A0, const float* __restrict__ B0, float* C0,
                    const float* __restrict__ A1, const float* __restrict__ B1, float* C1,
                    int lda, int ldb, int ldc, int kslab)
{
    constexpr int THREADS = (BM/TM)*(BN/TN);
    __shared__ float As[BK][BM];
    __shared__ float Bs[BK][BN];
    const float* A = blockIdx.z ? A1 : A0;
    const float* B = blockIdx.z ? B1 : B0;
    float* C = blockIdx.z ? C1 : C0;
    const int tid = threadIdx.x;
    const int bm  = blockIdx.y * BM;
    const int k_lo = blockIdx.x * kslab;
    const int tx = tid % (BN/TN);
    const int ty = tid / (BN/TN);

    float acc[TM][TN];
#pragma unroll
    for (int i = 0; i < TM; i++)
#pragma unroll
        for (int j = 0; j < TN; j++) acc[i][j] = 0.f;

    constexpr int A4 = BM*BK/4;
    constexpr int B4 = BN*BK/4;
    for (int k0 = k_lo; k0 < k_lo + kslab; k0 += BK) {
        for (int i = tid; i < A4; i += THREADS) {
            int r  = i / (BK/4);
            int kq = (i % (BK/4)) * 4;
            float4 v = *reinterpret_cast<const float4*>(A + (size_t)(bm+r)*lda + k0 + kq);
            As[kq+0][r] = v.x; As[kq+1][r] = v.y; As[kq+2][r] = v.z; As[kq+3][r] = v.w;
        }
        for (int i = tid; i < B4; i += THREADS) {
            int r  = i / (BK/4);
            int kq = (i % (BK/4)) * 4;
            float4 v = *reinterpret_cast<const float4*>(B + (size_t)r*ldb + k0 + kq);
            Bs[kq+0][r] = v.x; Bs[kq+1][r] = v.y; Bs[kq+2][r] = v.z; Bs[kq+3][r] = v.w;
        }
        __syncthreads();
#pragma unroll
        for (int k = 0; k < BK; k++) {
            float a[TM], b[TN];
#pragma unroll
            for (int i = 0; i < TM; i++) a[i] = As[k][ty*TM + i];
#pragma unroll
            for (int j = 0; j < TN; j++) b[j] = Bs[k][tx*TN + j];
#pragma unroll
            for (int i = 0; i < TM; i++)
#pragma unroll
                for (int j = 0; j < TN; j++)
                    acc[i][j] = fmaf(a[i], b[j], acc[i][j]);
        }
        __syncthreads();
    }
#pragma unroll
    for (int i = 0; i < TM; i++)
#pragma unroll
        for (int j = 0; j < TN; j++)
            atomicAdd(&C[(size_t)(bm + ty*TM + i)*ldc + tx*TN + j], acc[i][j]);
}

// ---------------------------------------------------------------------------
// Depthwise causal conv1d (k=4) + SiLU
// ---------------------------------------------------------------------------
__global__ void conv_silu_kernel(const float* __restrict__ cw_f, const float* __restrict__ cb_f,
                                 const float* __restrict__ cw_b, const float* __restrict__ cb_b)
{
    const int dir = blockIdx.y;
    const float* xz = g_xz[dir];
    const float* cw = dir ? cw_b : cw_f;
    const float* cb = dir ? cb_b : cb_f;
    float* xc = g_xc[dir];

    int idx = blockIdx.x * blockDim.x + threadIdx.x;
    int e = idx & (DINNER-1);
    int t = idx >> 11;
    int l = t & (SEQ-1);
    int base = t - l;

    float acc = cb[e];
#pragma unroll
    for (int k = 0; k < 4; k++) {
        int ls = l + k - 3;
        if (ls >= 0)
            acc = fmaf(cw[e*4 + k], xz[(size_t)(base + ls)*(2*DINNER) + e], acc);
    }
    acc = acc / (1.f + __expf(-acc));
    xc[idx] = acc;
}

// ---------------------------------------------------------------------------
// Selective scan + skip + gate; dA via r^k powers (A[n] = -(n+1) fast path).
// ---------------------------------------------------------------------------
__global__ void scan_kernel(const float* __restrict__ Alog_f, const float* __restrict__ D_f,
                            const float* __restrict__ Alog_b, const float* __restrict__ D_b)
{
    const int dir = blockIdx.z;
    const int b   = blockIdx.y;
    const int e   = blockIdx.x * blockDim.x + threadIdx.x;

    const float* delta = g_delta[dir];
    const float* xc    = g_xc[dir];
    const float* dbl   = g_dbl[dir];
    const float* xz    = g_xz[dir];
    __nv_bfloat16* ybf = g_ybf[dir];
    const float* Alog  = dir ? Alog_b : Alog_f;
    const float* Dp    = dir ? D_b    : D_f;

    float A[DSTATE], h[DSTATE];
    bool fast = true;
#pragma unroll
    for (int n = 0; n < DSTATE; n++) {
        A[n] = -expf(Alog[e*DSTATE + n]);
        h[n] = 0.f;
        fast = fast && (fabsf(A[n] + (float)(n+1)) < 1e-3f * (float)(n+1));
    }
    const float Dv = Dp[e];

    for (int l = 0; l < SEQ; l++) {
        const int t = b*SEQ + l;
        const float dlt = delta[(size_t)t*DINNER + e];
        const float xcv = xc[(size_t)t*DINNER + e];
        const float du  = dlt * xcv;
        const float* row = dbl + (size_t)t*96;

        float dA[DSTATE];
        if (fast) {
            const float r  = __expf(-dlt);
            const float r2 = r*r, r4 = r2*r2, r8 = r4*r4;
            dA[0]=r;        dA[1]=r2;       dA[2]=r2*r;     dA[3]=r4;
            dA[4]=r4*r;     dA[5]=r4*r2;    dA[6]=r4*dA[2]; dA[7]=r8;
            dA[8]=r8*r;     dA[9]=r8*r2;    dA[10]=r8*dA[2];dA[11]=r8*r4;
            dA[12]=r8*dA[4];dA[13]=r8*dA[5];dA[14]=r8*dA[6];dA[15]=r8*r8;
        } else {
#pragma unroll
            for (int n = 0; n < DSTATE; n++) dA[n] = __expf(dlt * A[n]);
        }

        float y0 = 0.f, y1 = 0.f, y2 = 0.f, y3 = 0.f;
#pragma unroll
        for (int n = 0; n < DSTATE; n += 4) {
            h[n+0] = fmaf(dA[n+0], h[n+0], du * row[64+n+0]);
            h[n+1] = fmaf(dA[n+1], h[n+1], du * row[64+n+1]);
            h[n+2] = fmaf(dA[n+2], h[n+2], du * row[64+n+2]);
            h[n+3] = fmaf(dA[n+3], h[n+3], du * row[64+n+3]);
            y0 = fmaf(h[n+0], row[80+n+0], y0);
            y1 = fmaf(h[n+1], row[80+n+1], y1);
            y2 = fmaf(h[n+2], row[80+n+2], y2);
            y3 = fmaf(h[n+3], row[80+n+3], y3);
        }
        float y = (y0 + y1) + (y2 + y3);

        const float zv = xz[(size_t)t*(2*DINNER) + DINNER + e];
        const float g  = zv / (1.f + __expf(-zv));
        float yv = (y + xcv*Dv) * g;

        __nv_bfloat16 hh = __float2bfloat16(yv);
        __nv_bfloat16 ll = __float2bfloat16(yv - __bfloat162float(hh));
        ybf[(size_t)t*(2*DINNER) + e]          = hh;
        ybf[(size_t)t*(2*DINNER) + DINNER + e] = ll;
    }
}

// ---------------------------------------------------------------------------
extern "C" void kernel_launch(void* const* d_in, const int* in_sizes, int n_in,
                              void* d_out, int out_size)
{
    const float* x       = (const float*)d_in[0];
    const float* f_inp   = (const float*)d_in[1];
    const float* f_cw    = (const float*)d_in[2];
    const float* f_cb    = (const float*)d_in[3];
    const float* f_xp    = (const float*)d_in[4];
    const float* f_dtw   = (const float*)d_in[5];
    const float* f_dtb   = (const float*)d_in[6];
    const float* f_Alog  = (const float*)d_in[7];
    const float* f_D     = (const float*)d_in[8];
    const float* f_op    = (const float*)d_in[9];
    const float* b_inp   = (const float*)d_in[10];
    const float* b_cw    = (const float*)d_in[11];
    const float* b_cb    = (const float*)d_in[12];
    const float* b_xp    = (const float*)d_in[13];
    const float* b_dtw   = (const float*)d_in[14];
    const float* b_dtb   = (const float*)d_in[15];
    const float* b_Alog  = (const float*)d_in[16];
    const float* b_D     = (const float*)d_in[17];
    const float* b_op    = (const float*)d_in[18];
    const float* merge_w = (const float*)d_in[19];
    float* out = (float*)d_out;

    void* p;
    cudaGetSymbolAddress(&p, g_xz);    float* xz0 = (float*)p; float* xz1 = xz0 + PLANE_XZ;
    cudaGetSymbolAddress(&p, g_dbl);   float* db0 = (float*)p; float* db1 = db0 + PLANE_DBL;
    cudaGetSymbolAddress(&p, g_delta); float* dl0 = (float*)p; float* dl1 = dl0 + PLANE_E;
    cudaGetSymbolAddress(&p, g_xc);    float* xc0 = (float*)p; float* xc1 = xc0 + PLANE_E;

    __nv_bfloat16 *xbf, *wbf0, *wbf1, *wdt0, *wdt1, *wop0, *wop1, *wmg,
                  *dtb0, *dtb1, *yb0, *yb1, *ocat;
    cudaGetSymbolAddress(&p, g_xbf);  xbf  = (__nv_bfloat16*)p;
    cudaGetSymbolAddress(&p, g_wbf);  wbf0 = (__nv_bfloat16*)p; wbf1 = wbf0 + (size_t)2*DINNER*2*DMODEL;
    cudaGetSymbolAddress(&p, g_wdt);  wdt0 = (__nv_bfloat16*)p; wdt1 = wdt0 + (size_t)DINNER*2*DTRANK;
    cudaGetSymbolAddress(&p, g_wop);  wop0 = (__nv_bfloat16*)p; wop1 = wop0 + (size_t)DMODEL*2*DINNER;
    cudaGetSymbolAddress(&p, g_wmg);  wmg  = (__nv_bfloat16*)p;
    cudaGetSymbolAddress(&p, g_dtbf); dtb0 = (__nv_bfloat16*)p; dtb1 = dtb0 + (size_t)TOK*2*DTRANK;
    cudaGetSymbolAddress(&p, g_ybf);  yb0  = (__nv_bfloat16*)p; yb1  = yb0  + (size_t)TOK*2*DINNER;
    cudaGetSymbolAddress(&p, g_ocat); ocat = (__nv_bfloat16*)p;

    cudaFuncSetAttribute((const void*)gemm_bf16s<false,false>, cudaFuncAttributeMaxDynamicSharedMemorySize, GSMEM);
    cudaFuncSetAttribute((const void*)gemm_bf16s<true ,false>, cudaFuncAttributeMaxDynamicSharedMemorySize, GSMEM);
    cudaFuncSetAttribute((const void*)gemm_bf16s<false,true >, cudaFuncAttributeMaxDynamicSharedMemorySize, GSMEM);

    // launches 1-5 (so launch 6 = in_proj GEMM lands in the ncu window)
    cudaMemsetAsync(db0, 0, 2 * PLANE_DBL * sizeof(float));                      // 1
    cvt_split<<<(TOK*DMODEL)/1024, 256>>>(x, xbf, DMODEL);                       // 2
    cvt_split<<<((size_t)2*DINNER*DMODEL)/1024, 256>>>(f_inp, wbf0, DMODEL);     // 3
    cvt_split<<<((size_t)2*DINNER*DMODEL)/1024, 256>>>(b_inp, wbf1, DMODEL);     // 4
    cvt_split<<<((size_t)DINNER*DTRANK)/1024, 256>>>(f_dtw, wdt0, DTRANK);       // 5

    // 6) in_proj both dirs: xz = X @ in_proj^T  (M=2048, N=4096, K=1024)
    {
        dim3 grid(4096/128, TOK/128, 2);
        gemm_bf16s<false,false><<<grid,256,GSMEM>>>(
            xbf, xbf, wbf0, wbf1, xz0, xz1, 2*DINNER,
            nullptr, nullptr, 0, 0, DMODEL, nullptr, nullptr,
            /*flipa*/0, 1, /*flipc*/0, 0);
    }

    // remaining converts
    cvt_split<<<((size_t)DINNER*DTRANK)/1024, 256>>>(b_dtw, wdt1, DTRANK);
    cvt_split<<<((size_t)DMODEL*DINNER)/1024, 256>>>(f_op, wop0, DINNER);
    cvt_split<<<((size_t)DMODEL*DINNER)/1024, 256>>>(b_op, wop1, DINNER);
    cvt_split<<<((size_t)DMODEL*2*DMODEL)/1024, 256>>>(merge_w, wmg, 2*DMODEL);

    // depthwise conv + SiLU (both dirs)
    {
        dim3 grid((TOK*DINNER)/256, 2);
        conv_silu_kernel<<<grid,256>>>(f_cw, f_cb, b_cw, b_cb);
    }

    // x_proj both dirs: dbl = xc @ x_proj^T  (M=2048, N=96, K=2048), split-K=8
    {
        dim3 grid(8, TOK/32, 2);
        gemm_nt_atomic<32,96,16,2,6><<<grid,256>>>(
            xc0, f_xp, db0, xc1, b_xp, db1, DINNER, DINNER, 96, DINNER/8);
    }

    // split dt columns of dbl (both dirs)
    {
        dim3 grid((TOK*DTRANK)/1024, 2);
        cvt_dt<<<grid, 256>>>(db0, dtb0, db1, dtb1);
    }

    // dt projection + fused bias/softplus, both dirs (M=2048, N=2048, K=64)
    {
        dim3 grid(DINNER/128, TOK/128, 2);
        gemm_bf16s<true,false><<<grid,256,GSMEM>>>(
            dtb0, dtb1, wdt0, wdt1, dl0, dl1, DINNER,
            nullptr, nullptr, 0, 0, DTRANK, f_dtb, b_dtb, 0, 0, 0, 0);
    }

    // selective scan + skip + gate -> ybf (split)
    {
        dim3 grid(DINNER/128, BSZ, 2);
        scan_kernel<<<grid,128>>>(f_Alog, f_D, b_Alog, b_D);
    }

    // out_proj both dirs (M=2048, N=1024, K=2048) -> ocat split, bwd flipped
    {
        dim3 grid(DMODEL/128, TOK/128, 2);
        gemm_bf16s<false,true><<<grid,256,GSMEM>>>(
            yb0, yb1, wop0, wop1, nullptr, nullptr, 0,
            ocat, ocat + DMODEL, 2*(2*DMODEL), 2*DMODEL, DINNER,
            nullptr, nullptr, 0, 0, /*flipc*/0, 1);
    }

    // merge: out = [f | flip(b)] @ merge_w^T  (M=2048, N=1024, K=2048)
    {
        dim3 grid(DMODEL/128, TOK/128, 1);
        gemm_bf16s<false,false><<<grid,256,GSMEM>>>(
            ocat, ocat, wmg, wmg, out, out, DMODEL,
            nullptr, nullptr, 0, 0, 2*DMODEL, nullptr, nullptr, 0, 0, 0, 0);
    }
}

// round 8
// speedup vs baseline: 1.1209x; 1.1209x over previous
#include <cuda_runtime.h>
#include <cuda_fp16.h>
#include <cstdint>

// ===========================================================================
// BiMamba via mma.sync fp16 2-product GEMMs:
//   A (activations) stored exactly as fp16 hi/lo pair [hi(K)|lo(K)],
//   B (weights) stored as plain fp16.  C = Ah*B + Al*B = A*B + O(B fp16 rnd).
// 3-stage cp.async pipeline, dual-direction launches via blockIdx.z.
// B=2, L=1024, D_MODEL=1024, D_INNER=2048, DT_RANK=64, D_STATE=16
// ===========================================================================

#define BSZ     2
#define SEQ     1024
#define DMODEL  1024
#define DINNER  2048
#define DTRANK  64
#define DSTATE  16
#define TOK     (BSZ*SEQ)

#define PLANE_XZ   ((size_t)TOK * (2*DINNER))
#define PLANE_E    ((size_t)TOK * DINNER)
#define PLANE_DBL  ((size_t)TOK * 96)

// fp32 intermediates
__device__ float g_xz[2][PLANE_XZ];     // xi | z per direction
__device__ float g_xc[2][PLANE_E];      // conv+silu output
__device__ float g_dbl[2][PLANE_DBL];   // dt(64) | B(16) | C(16)
__device__ float g_delta[2][PLANE_E];   // softplus(dt@dt_w + b)

// fp16 operands
__device__ __half g_xhl [(size_t)TOK * 2*DMODEL];        // x hi/lo
__device__ __half g_win [2][(size_t)2*DINNER * DMODEL];  // in_proj w (plain)
__device__ __half g_wdt [2][(size_t)DINNER * DTRANK];    // dt_w (plain)
__device__ __half g_wop [2][(size_t)DMODEL * DINNER];    // out_proj w (plain)
__device__ __half g_wmg [(size_t)DMODEL * (2*DMODEL)];   // merge_w (plain)
__device__ __half g_dthl[2][(size_t)TOK * 2*DTRANK];     // dt cols hi/lo
__device__ __half g_yhl [2][(size_t)TOK * 2*DINNER];     // scan out hi/lo
__device__ __half g_ocat[(size_t)TOK * 2*(2*DMODEL)];    // [f|flip(b)] hi/lo

// ---------------------------------------------------------------------------
// asm helpers
// ---------------------------------------------------------------------------
__device__ __forceinline__ void ldsm_x4(uint32_t* r, uint32_t addr) {
    asm volatile("ldmatrix.sync.aligned.m8n8.x4.shared.b16 {%0,%1,%2,%3}, [%4];"
        : "=r"(r[0]), "=r"(r[1]), "=r"(r[2]), "=r"(r[3]) : "r"(addr));
}
__device__ __forceinline__ void mma16816(float* c, const uint32_t* a, const uint32_t* b) {
    asm volatile(
        "mma.sync.aligned.m16n8k16.row.col.f32.f16.f16.f32 "
        "{%0,%1,%2,%3}, {%4,%5,%6,%7}, {%8,%9}, {%0,%1,%2,%3};"
        : "+f"(c[0]), "+f"(c[1]), "+f"(c[2]), "+f"(c[3])
        : "r"(a[0]), "r"(a[1]), "r"(a[2]), "r"(a[3]), "r"(b[0]), "r"(b[1]));
}
#define CP_ASYNC16(dst, src) \
    asm volatile("cp.async.cg.shared.global [%0], [%1], 16;" :: "r"(dst), "l"(src))
#define CP_COMMIT() asm volatile("cp.async.commit_group;" ::: "memory")
#define CP_WAIT1()  asm volatile("cp.async.wait_group 1;" ::: "memory")
#define CP_WAIT0()  asm volatile("cp.async.wait_group 0;" ::: "memory")

// ---------------------------------------------------------------------------
// Main GEMM: 128x128 tile, virtual K' = 2K (Ah*B, Al*B), BK=64 chunks,
// 3-stage cp.async ring, 8 warps (2x4). A rows are [hi(K)|lo(K)], B rows K.
// ---------------------------------------------------------------------------
#define GSMEM (3*32768)

template<bool SOFTPLUS, bool OUTHL>
__global__ __launch_bounds__(256)
void gemm_f16(const __half* __restrict__ A0, const __half* __restrict__ A1,
              const __half* __restrict__ B0, const __half* __restrict__ B1,
              float* C0, float* C1, int ldc,
              __half* Cb0, __half* Cb1, int ldcb, int koffb,
              int K, const float* bias0, const float* bias1,
              int flipa0, int flipa1, int flipc0, int flipc1)
{
    extern __shared__ __align__(128) char smem_raw[];
    const uint32_t sbase = (uint32_t)__cvta_generic_to_shared(smem_raw);

    const int z = blockIdx.z;
    const __half* A = z ? A1 : A0;
    const __half* B = z ? B1 : B0;
    float* C = z ? C1 : C0;
    __half* Cb = z ? Cb1 : Cb0;
    const float* bias = z ? bias1 : bias0;
    const int flipa = z ? flipa1 : flipa0;
    const int flipc = z ? flipc1 : flipc0;

    const int tid = threadIdx.x;
    const int wid = tid >> 5;
    const int lid = tid & 31;
    const int bm = blockIdx.y * 128;
    const int bn = blockIdx.x * 128;

    const int wm = wid >> 2;
    const int wn = wid & 3;
    const int mbase = wm * 64;
    const int nbase = wn * 32;

    const int qrow = lid & 15;
    const int qc16 = lid >> 4;

    const int lda2 = 2 * K;
    const int nk = K >> 6;
    const int nv = 2 * nk;

    float acc[4][4][4];
#pragma unroll
    for (int f = 0; f < 4; f++)
#pragma unroll
        for (int g = 0; g < 4; g++)
#pragma unroll
            for (int e = 0; e < 4; e++) acc[f][g][e] = 0.f;

    auto sA = [&](int st) -> uint32_t { return sbase + (uint32_t)st * 32768u; };
    auto sB = [&](int st) -> uint32_t { return sbase + (uint32_t)st * 32768u + 16384u; };

    auto load_stage = [&](int v, int st) {
        int aoff, boff;
        if (v < nk) { aoff = v << 6;               boff = v << 6; }
        else        { aoff = K + ((v - nk) << 6);  boff = (v - nk) << 6; }
        uint32_t da = sA(st), db = sB(st);
#pragma unroll
        for (int i = 0; i < 4; i++) {
            int ch  = tid + (i << 8);
            int r   = ch >> 3;
            int c16 = ch & 7;
            uint32_t sw = (uint32_t)((c16 ^ (r & 7)) << 4) + (uint32_t)(r << 7);
            int gm = bm + r;
            int am = flipa ? (gm ^ (SEQ-1)) : gm;
            CP_ASYNC16(da + sw, A + (size_t)am * lda2 + aoff + (c16 << 3));
            CP_ASYNC16(db + sw, B + (size_t)(bn + r) * K + boff + (c16 << 3));
        }
    };

    auto compute_stage = [&](int st) {
        uint32_t sa = sA(st), sb = sB(st);
#pragma unroll
        for (int s = 0; s < 4; s++) {
            uint32_t bq[2][4];
#pragma unroll
            for (int g2 = 0; g2 < 2; g2++) {
                int r = nbase + g2*16 + qrow;
                int c = (s << 1) + qc16;
                ldsm_x4(bq[g2], sb + (uint32_t)(r << 7) + (uint32_t)((c ^ (r & 7)) << 4));
            }
#pragma unroll
            for (int f = 0; f < 4; f++) {
                int r = mbase + f*16 + qrow;
                int c = (s << 1) + qc16;
                uint32_t afr[4];
                ldsm_x4(afr, sa + (uint32_t)(r << 7) + (uint32_t)((c ^ (r & 7)) << 4));
#pragma unroll
                for (int g = 0; g < 4; g++) {
                    uint32_t bfr[2] = { bq[g >> 1][g & 1], bq[g >> 1][(g & 1) + 2] };
                    mma16816(acc[f][g], afr, bfr);
                }
            }
        }
    };

    load_stage(0, 0); CP_COMMIT();
    if (nv > 1) { load_stage(1, 1); CP_COMMIT(); }

    for (int v = 0; v < nv; v++) {
        int st = v % 3;
        if (v < nv - 1) CP_WAIT1(); else CP_WAIT0();
        __syncthreads();
        compute_stage(st);
        int vn = v + 2;
        if (vn < nv) { load_stage(vn, vn % 3); CP_COMMIT(); }
    }

    // ---- epilogue ----
    const int crow = lid >> 2;
    const int ccol = (lid & 3) * 2;
#pragma unroll
    for (int f = 0; f < 4; f++) {
        int m0 = bm + mbase + f*16 + crow;
        int m1 = m0 + 8;
        int gm0 = flipc ? (m0 ^ (SEQ-1)) : m0;
        int gm1 = flipc ? (m1 ^ (SEQ-1)) : m1;
#pragma unroll
        for (int g = 0; g < 4; g++) {
            int n = bn + nbase + g*8 + ccol;
            float v0 = acc[f][g][0], v1 = acc[f][g][1];
            float v2 = acc[f][g][2], v3 = acc[f][g][3];
            if (SOFTPLUS) {
                float b0 = bias[n], b1 = bias[n+1];
                float x0 = v0 + b0, x1 = v1 + b1, x2 = v2 + b0, x3 = v3 + b1;
                v0 = (x0 > 20.f) ? x0 : log1pf(__expf(x0));
                v1 = (x1 > 20.f) ? x1 : log1pf(__expf(x1));
                v2 = (x2 > 20.f) ? x2 : log1pf(__expf(x2));
                v3 = (x3 > 20.f) ? x3 : log1pf(__expf(x3));
            }
            if (OUTHL) {
                __half h0 = __float2half_rn(v0), h1 = __float2half_rn(v1);
                __half h2 = __float2half_rn(v2), h3 = __float2half_rn(v3);
                __half l0 = __float2half_rn(v0 - __half2float(h0));
                __half l1 = __float2half_rn(v1 - __half2float(h1));
                __half l2 = __float2half_rn(v2 - __half2float(h2));
                __half l3 = __float2half_rn(v3 - __half2float(h3));
                *reinterpret_cast<__half2*>(Cb + (size_t)gm0*ldcb + n)         = __halves2half2(h0, h1);
                *reinterpret_cast<__half2*>(Cb + (size_t)gm0*ldcb + koffb + n) = __halves2half2(l0, l1);
                *reinterpret_cast<__half2*>(Cb + (size_t)gm1*ldcb + n)         = __halves2half2(h2, h3);
                *reinterpret_cast<__half2*>(Cb + (size_t)gm1*ldcb + koffb + n) = __halves2half2(l2, l3);
            } else {
                *reinterpret_cast<float2*>(C + (size_t)gm0*ldc + n) = make_float2(v0, v1);
                *reinterpret_cast<float2*>(C + (size_t)gm1*ldc + n) = make_float2(v2, v3);
            }
        }
    }
}

// ---------------------------------------------------------------------------
// fp32 -> [hi(K)|lo(K)] fp16 split (A-side operands)
// ---------------------------------------------------------------------------
__global__ void cvt_split(const float* __restrict__ in, __half* __restrict__ out, int K)
{
    int idx = (blockIdx.x * blockDim.x + threadIdx.x) << 2;
    int row = idx / K;
    int col = idx - row * K;
    float4 v = *reinterpret_cast<const float4*>(in + idx);
    __half h0 = __float2half_rn(v.x), h1 = __float2half_rn(v.y);
    __half h2 = __float2half_rn(v.z), h3 = __float2half_rn(v.w);
    __half l0 = __float2half_rn(v.x - __half2float(h0));
    __half l1 = __float2half_rn(v.y - __half2float(h1));
    __half l2 = __float2half_rn(v.z - __half2float(h2));
    __half l3 = __float2half_rn(v.w - __half2float(h3));
    size_t o = (size_t)row * 2 * K + col;
    *reinterpret_cast<__half2*>(out + o)         = __halves2half2(h0, h1);
    *reinterpret_cast<__half2*>(out + o + 2)     = __halves2half2(h2, h3);
    *reinterpret_cast<__half2*>(out + o + K)     = __halves2half2(l0, l1);
    *reinterpret_cast<__half2*>(out + o + K + 2) = __halves2half2(l2, l3);
}

// fp32 -> plain fp16 (B-side weights), flat
__global__ void cvt_w(const float* __restrict__ in, __half* __restrict__ out)
{
    int idx = (blockIdx.x * blockDim.x + threadIdx.x) << 2;
    float4 v = *reinterpret_cast<const float4*>(in + idx);
    __half2 a = __halves2half2(__float2half_rn(v.x), __float2half_rn(v.y));
    __half2 b = __halves2half2(__float2half_rn(v.z), __float2half_rn(v.w));
    *reinterpret_cast<__half2*>(out + idx)     = a;
    *reinterpret_cast<__half2*>(out + idx + 2) = b;
}

// dbl (stride 96, cols 0..63) -> packed 2048 x 128 fp16 hi/lo; both dirs
__global__ void cvt_dt(const float* __restrict__ in0, __half* __restrict__ out0,
                       const float* __restrict__ in1, __half* __restrict__ out1)
{
    const float* in = blockIdx.y ? in1 : in0;
    __half* out = blockIdx.y ? out1 : out0;
    int idx = (blockIdx.x * blockDim.x + threadIdx.x) << 2;
    int row = idx >> 6;
    int col = idx & 63;
    float4 v = *reinterpret_cast<const float4*>(in + (size_t)row * 96 + col);
    __half h0 = __float2half_rn(v.x), h1 = __float2half_rn(v.y);
    __half h2 = __float2half_rn(v.z), h3 = __float2half_rn(v.w);
    __half l0 = __float2half_rn(v.x - __half2float(h0));
    __half l1 = __float2half_rn(v.y - __half2float(h1));
    __half l2 = __float2half_rn(v.z - __half2float(h2));
    __half l3 = __float2half_rn(v.w - __half2float(h3));
    size_t o = (size_t)row * 128 + col;
    *reinterpret_cast<__half2*>(out + o)          = __halves2half2(h0, h1);
    *reinterpret_cast<__half2*>(out + o + 2)      = __halves2half2(h2, h3);
    *reinterpret_cast<__half2*>(out + o + 64)     = __halves2half2(l0, l1);
    *reinterpret_cast<__half2*>(out + o + 64 + 2) = __halves2half2(l2, l3);
}

// ---------------------------------------------------------------------------
// Small split-K fp32 GEMM with atomicAdd epilogue (x_proj), both dirs (grid.z)
// ---------------------------------------------------------------------------
template<int BM,int BN,int BK,int TM,int TN>
__global__ __launch_bounds__((BM/TM)*(BN/TN))
void gemm_nt_atomic(const float* __restrict__ A0, const float* __restrict__ B0, float* C0,
                    const float* __restrict__ A1, const float* __restrict__ B1, float* C1,
                    int lda, int ldb, int ldc, int kslab)
{
    constexpr int THREADS = (BM/TM)*(BN/TN);
    __shared__ float As[BK][BM];
    __shared__ float Bs[BK][BN];
    const float* A = blockIdx.z ? A1 : A0;
    const float* B = blockIdx.z ? B1 : B0;
    float* C = blockIdx.z ? C1 : C0;
    const int tid = threadIdx.x;
    const int bm  = blockIdx.y * BM;
    const int k_lo = blockIdx.x * kslab;
    const int tx = tid % (BN/TN);
    const int ty = tid / (BN/TN);

    float acc[TM][TN];
#pragma unroll
    for (int i = 0; i < TM; i++)
#pragma unroll
        for (int j = 0; j < TN; j++) acc[i][j] = 0.f;

    constexpr int A4 = BM*BK/4;
    constexpr int B4 = BN*BK/4;
    for (int k0 = k_lo; k0 < k_lo + kslab; k0 += BK) {
        for (int i = tid; i < A4; i += THREADS) {
            int r  = i / (BK/4);
            int kq = (i % (BK/4)) * 4;
            float4 v = *reinterpret_cast<const float4*>(A + (size_t)(bm+r)*lda + k0 + kq);
            As[kq+0][r] = v.x; As[kq+1][r] = v.y; As[kq+2][r] = v.z; As[kq+3][r] = v.w;
        }
        for (int i = tid; i < B4; i += THREADS) {
            int r  = i / (BK/4);
            int kq = (i % (BK/4)) * 4;
            float4 v = *reinterpret_cast<const float4*>(B + (size_t)r*ldb + k0 + kq);
            Bs[kq+0][r] = v.x; Bs[kq+1][r] = v.y; Bs[kq+2][r] = v.z; Bs[kq+3][r] = v.w;
        }
        __syncthreads();
#pragma unroll
        for (int k = 0; k < BK; k++) {
            float a[TM], b[TN];
#pragma unroll
            for (int i = 0; i < TM; i++) a[i] = As[k][ty*TM + i];
#pragma unroll
            for (int j = 0; j < TN; j++) b[j] = Bs[k][tx*TN + j];
#pragma unroll
            for (int i = 0; i < TM; i++)
#pragma unroll
                for (int j = 0; j < TN; j++)
                    acc[i][j] = fmaf(a[i], b[j], acc[i][j]);
        }
        __syncthreads();
    }
#pragma unroll
    for (int i = 0; i < TM; i++)
#pragma unroll
        for (int j = 0; j < TN; j++)
            atomicAdd(&C[(size_t)(bm + ty*TM + i)*ldc + tx*TN + j], acc[i][j]);
}

// ---------------------------------------------------------------------------
// Depthwise causal conv1d (k=4) + SiLU
// ---------------------------------------------------------------------------
__global__ void conv_silu_kernel(const float* __restrict__ cw_f, const float* __restrict__ cb_f,
                                 const float* __restrict__ cw_b, const float* __restrict__ cb_b)
{
    const int dir = blockIdx.y;
    const float* xz = g_xz[dir];
    const float* cw = dir ? cw_b : cw_f;
    const float* cb = dir ? cb_b : cb_f;
    float* xc = g_xc[dir];

    int idx = blockIdx.x * blockDim.x + threadIdx.x;
    int e = idx & (DINNER-1);
    int t = idx >> 11;
    int l = t & (SEQ-1);
    int base = t - l;

    float acc = cb[e];
#pragma unroll
    for (int k = 0; k < 4; k++) {
        int ls = l + k - 3;
        if (ls >= 0)
            acc = fmaf(cw[e*4 + k], xz[(size_t)(base + ls)*(2*DINNER) + e], acc);
    }
    acc = acc / (1.f + __expf(-acc));
    xc[idx] = acc;
}

// ---------------------------------------------------------------------------
// Selective scan + skip + gate; dA via r^k powers (A[n] = -(n+1) fast path).
// Writes y as fp16 hi/lo.
// ---------------------------------------------------------------------------
__global__ void scan_kernel(const float* __restrict__ Alog_f, const float* __restrict__ D_f,
                            const float* __restrict__ Alog_b, const float* __restrict__ D_b)
{
    const int dir = blockIdx.z;
    const int b   = blockIdx.y;
    const int e   = blockIdx.x * blockDim.x + threadIdx.x;

    const float* delta = g_delta[dir];
    const float* xc    = g_xc[dir];
    const float* dbl   = g_dbl[dir];
    const float* xz    = g_xz[dir];
    __half* yhl        = g_yhl[dir];
    const float* Alog  = dir ? Alog_b : Alog_f;
    const float* Dp    = dir ? D_b    : D_f;

    float A[DSTATE], h[DSTATE];
    bool fast = true;
#pragma unroll
    for (int n = 0; n < DSTATE; n++) {
        A[n] = -expf(Alog[e*DSTATE + n]);
        h[n] = 0.f;
        fast = fast && (fabsf(A[n] + (float)(n+1)) < 1e-3f * (float)(n+1));
    }
    const float Dv = Dp[e];

    for (int l = 0; l < SEQ; l++) {
        const int t = b*SEQ + l;
        const float dlt = delta[(size_t)t*DINNER + e];
        const float xcv = xc[(size_t)t*DINNER + e];
        const float du  = dlt * xcv;
        const float* row = dbl + (size_t)t*96;

        float dA[DSTATE];
        if (fast) {
            const float r  = __expf(-dlt);
            const float r2 = r*r, r4 = r2*r2, r8 = r4*r4;
            dA[0]=r;        dA[1]=r2;       dA[2]=r2*r;     dA[3]=r4;
            dA[4]=r4*r;     dA[5]=r4*r2;    dA[6]=r4*dA[2]; dA[7]=r8;
            dA[8]=r8*r;     dA[9]=r8*r2;    dA[10]=r8*dA[2];dA[11]=r8*r4;
            dA[12]=r8*dA[4];dA[13]=r8*dA[5];dA[14]=r8*dA[6];dA[15]=r8*r8;
        } else {
#pragma unroll
            for (int n = 0; n < DSTATE; n++) dA[n] = __expf(dlt * A[n]);
        }

        float y0 = 0.f, y1 = 0.f, y2 = 0.f, y3 = 0.f;
#pragma unroll
        for (int n = 0; n < DSTATE; n += 4) {
            h[n+0] = fmaf(dA[n+0], h[n+0], du * row[64+n+0]);
            h[n+1] = fmaf(dA[n+1], h[n+1], du * row[64+n+1]);
            h[n+2] = fmaf(dA[n+2], h[n+2], du * row[64+n+2]);
            h[n+3] = fmaf(dA[n+3], h[n+3], du * row[64+n+3]);
            y0 = fmaf(h[n+0], row[80+n+0], y0);
            y1 = fmaf(h[n+1], row[80+n+1], y1);
            y2 = fmaf(h[n+2], row[80+n+2], y2);
            y3 = fmaf(h[n+3], row[80+n+3], y3);
        }
        float y = (y0 + y1) + (y2 + y3);

        const float zv = xz[(size_t)t*(2*DINNER) + DINNER + e];
        const float g  = zv / (1.f + __expf(-zv));
        float yv = (y + xcv*Dv) * g;

        __half hh = __float2half_rn(yv);
        __half ll = __float2half_rn(yv - __half2float(hh));
        yhl[(size_t)t*(2*DINNER) + e]          = hh;
        yhl[(size_t)t*(2*DINNER) + DINNER + e] = ll;
    }
}

// ---------------------------------------------------------------------------
extern "C" void kernel_launch(void* const* d_in, const int* in_sizes, int n_in,
                              void* d_out, int out_size)
{
    const float* x       = (const float*)d_in[0];
    const float* f_inp   = (const float*)d_in[1];
    const float* f_cw    = (const float*)d_in[2];
    const float* f_cb    = (const float*)d_in[3];
    const float* f_xp    = (const float*)d_in[4];
    const float* f_dtw   = (const float*)d_in[5];
    const float* f_dtb   = (const float*)d_in[6];
    const float* f_Alog  = (const float*)d_in[7];
    const float* f_D     = (const float*)d_in[8];
    const float* f_op    = (const float*)d_in[9];
    const float* b_inp   = (const float*)d_in[10];
    const float* b_cw    = (const float*)d_in[11];
    const float* b_cb    = (const float*)d_in[12];
    const float* b_xp    = (const float*)d_in[13];
    const float* b_dtw   = (const float*)d_in[14];
    const float* b_dtb   = (const float*)d_in[15];
    const float* b_Alog  = (const float*)d_in[16];
    const float* b_D     = (const float*)d_in[17];
    const float* b_op    = (const float*)d_in[18];
    const float* merge_w = (const float*)d_in[19];
    float* out = (float*)d_out;

    void* p;
    cudaGetSymbolAddress(&p, g_xz);    float* xz0 = (float*)p; float* xz1 = xz0 + PLANE_XZ;
    cudaGetSymbolAddress(&p, g_dbl);   float* db0 = (float*)p; float* db1 = db0 + PLANE_DBL;
    cudaGetSymbolAddress(&p, g_delta); float* dl0 = (float*)p; float* dl1 = dl0 + PLANE_E;
    cudaGetSymbolAddress(&p, g_xc);    float* xc0 = (float*)p; float* xc1 = xc0 + PLANE_E;

    __half *xhl, *win0, *win1, *wdt0, *wdt1, *wop0, *wop1, *wmg,
           *dth0, *dth1, *yh0, *yh1, *ocat;
    cudaGetSymbolAddress(&p, g_xhl);  xhl  = (__half*)p;
    cudaGetSymbolAddress(&p, g_win);  win0 = (__half*)p; win1 = win0 + (size_t)2*DINNER*DMODEL;
    cudaGetSymbolAddress(&p, g_wdt);  wdt0 = (__half*)p; wdt1 = wdt0 + (size_t)DINNER*DTRANK;
    cudaGetSymbolAddress(&p, g_wop);  wop0 = (__half*)p; wop1 = wop0 + (size_t)DMODEL*DINNER;
    cudaGetSymbolAddress(&p, g_wmg);  wmg  = (__half*)p;
    cudaGetSymbolAddress(&p, g_dthl); dth0 = (__half*)p; dth1 = dth0 + (size_t)TOK*2*DTRANK;
    cudaGetSymbolAddress(&p, g_yhl);  yh0  = (__half*)p; yh1  = yh0  + (size_t)TOK*2*DINNER;
    cudaGetSymbolAddress(&p, g_ocat); ocat = (__half*)p;

    cudaFuncSetAttribute((const void*)gemm_f16<false,false>, cudaFuncAttributeMaxDynamicSharedMemorySize, GSMEM);
    cudaFuncSetAttribute((const void*)gemm_f16<true ,false>, cudaFuncAttributeMaxDynamicSharedMemorySize, GSMEM);
    cudaFuncSetAttribute((const void*)gemm_f16<false,true >, cudaFuncAttributeMaxDynamicSharedMemorySize, GSMEM);

    // memset (not counted by ncu) + 5 converts, so the in_proj GEMM is the
    // 6th kernel launch (ncu -s 5 -c 1 profiles it).
    cudaMemsetAsync(db0, 0, 2 * PLANE_DBL * sizeof(float));
    cvt_split<<<(TOK*DMODEL)/1024, 256>>>(x, xhl, DMODEL);                       // 1
    cvt_w<<<((size_t)2*DINNER*DMODEL)/1024, 256>>>(f_inp, win0);                 // 2
    cvt_w<<<((size_t)2*DINNER*DMODEL)/1024, 256>>>(b_inp, win1);                 // 3
    cvt_w<<<((size_t)DINNER*DTRANK)/1024, 256>>>(f_dtw, wdt0);                   // 4
    cvt_w<<<((size_t)DINNER*DTRANK)/1024, 256>>>(b_dtw, wdt1);                   // 5

    // 6) in_proj both dirs: xz = X @ in_proj^T  (M=2048, N=4096, K=1024)
    {
        dim3 grid(4096/128, TOK/128, 2);
        gemm_f16<false,false><<<grid,256,GSMEM>>>(
            xhl, xhl, win0, win1, xz0, xz1, 2*DINNER,
            nullptr, nullptr, 0, 0, DMODEL, nullptr, nullptr,
            /*flipa*/0, 1, /*flipc*/0, 0);
    }

    // remaining weight converts
    cvt_w<<<((size_t)DMODEL*DINNER)/1024, 256>>>(f_op, wop0);
    cvt_w<<<((size_t)DMODEL*DINNER)/1024, 256>>>(b_op, wop1);
    cvt_w<<<((size_t)DMODEL*2*DMODEL)/1024, 256>>>(merge_w, wmg);

    // depthwise conv + SiLU (both dirs)
    {
        dim3 grid((TOK*DINNER)/256, 2);
        conv_silu_kernel<<<grid,256>>>(f_cw, f_cb, b_cw, b_cb);
    }

    // x_proj both dirs: dbl = xc @ x_proj^T  (M=2048, N=96, K=2048), split-K=8
    {
        dim3 grid(8, TOK/32, 2);
        gemm_nt_atomic<32,96,16,2,6><<<grid,256>>>(
            xc0, f_xp, db0, xc1, b_xp, db1, DINNER, DINNER, 96, DINNER/8);
    }

    // split dt columns of dbl (both dirs)
    {
        dim3 grid((TOK*DTRANK)/1024, 2);
        cvt_dt<<<grid, 256>>>(db0, dth0, db1, dth1);
    }

    // dt projection + fused bias/softplus, both dirs (M=2048, N=2048, K=64)
    {
        dim3 grid(DINNER/128, TOK/128, 2);
        gemm_f16<true,false><<<grid,256,GSMEM>>>(
            dth0, dth1, wdt0, wdt1, dl0, dl1, DINNER,
            nullptr, nullptr, 0, 0, DTRANK, f_dtb, b_dtb, 0, 0, 0, 0);
    }

    // selective scan + skip + gate -> yhl (fp16 hi/lo)
    {
        dim3 grid(DINNER/128, BSZ, 2);
        scan_kernel<<<grid,128>>>(f_Alog, f_D, b_Alog, b_D);
    }

    // out_proj both dirs (M=2048, N=1024, K=2048) -> ocat hi/lo, bwd flipped
    {
        dim3 grid(DMODEL/128, TOK/128, 2);
        gemm_f16<false,true><<<grid,256,GSMEM>>>(
            yh0, yh1, wop0, wop1, nullptr, nullptr, 0,
            ocat, ocat + DMODEL, 2*(2*DMODEL), 2*DMODEL, DINNER,
            nullptr, nullptr, 0, 0, /*flipc*/0, 1);
    }

    // merge: out = [f | flip(b)] @ merge_w^T  (M=2048, N=1024, K=2048)
    {
        dim3 grid(DMODEL/128, TOK/128, 1);
        gemm_f16<false,false><<<grid,256,GSMEM>>>(
            ocat, ocat, wmg, wmg, out, out, DMODEL,
            nullptr, nullptr, 0, 0, 2*DMODEL, nullptr, nullptr, 0, 0, 0, 0);
    }
}

// round 9
// speedup vs baseline: 1.1373x; 1.0146x over previous
#include <cuda_runtime.h>
#include <cuda_fp16.h>
#include <cstdint>

// ===========================================================================
// BiMamba via mma.sync fp16 2-product GEMMs:
//   A (activations) stored exactly as fp16 hi/lo pair [hi(K)|lo(K)],
//   B (weights) stored as plain fp16.  C = Ah*B + Al*B = A*B + O(B fp16 rnd).
// 3-stage cp.async pipeline, dual-direction launches, 2 CTAs/SM residency.
// B=2, L=1024, D_MODEL=1024, D_INNER=2048, DT_RANK=64, D_STATE=16
// ===========================================================================

#define BSZ     2
#define SEQ     1024
#define DMODEL  1024
#define DINNER  2048
#define DTRANK  64
#define DSTATE  16
#define TOK     (BSZ*SEQ)

#define PLANE_XZ   ((size_t)TOK * (2*DINNER))
#define PLANE_E    ((size_t)TOK * DINNER)
#define PLANE_DBL  ((size_t)TOK * 96)

// fp32 intermediates
__device__ float g_xz[2][PLANE_XZ];     // xi | z per direction
__device__ float g_xc[2][PLANE_E];      // conv+silu output
__device__ float g_dbl[2][PLANE_DBL];   // dt(64) | B(16) | C(16)
__device__ float g_delta[2][PLANE_E];   // softplus(dt@dt_w + b)

// fp16 operands
__device__ __half g_xhl [(size_t)TOK * 2*DMODEL];        // x hi/lo
__device__ __half g_win [2][(size_t)2*DINNER * DMODEL];  // in_proj w (plain)
__device__ __half g_wdt [2][(size_t)DINNER * DTRANK];    // dt_w (plain)
__device__ __half g_wop [2][(size_t)DMODEL * DINNER];    // out_proj w (plain)
__device__ __half g_wmg [(size_t)DMODEL * (2*DMODEL)];   // merge_w (plain)
__device__ __half g_dthl[2][(size_t)TOK * 2*DTRANK];     // dt cols hi/lo
__device__ __half g_yhl [2][(size_t)TOK * 2*DINNER];     // scan out hi/lo
__device__ __half g_ocat[(size_t)TOK * 2*(2*DMODEL)];    // [f|flip(b)] hi/lo

// ---------------------------------------------------------------------------
// asm helpers
// ---------------------------------------------------------------------------
__device__ __forceinline__ void ldsm_x4(uint32_t* r, uint32_t addr) {
    asm volatile("ldmatrix.sync.aligned.m8n8.x4.shared.b16 {%0,%1,%2,%3}, [%4];"
        : "=r"(r[0]), "=r"(r[1]), "=r"(r[2]), "=r"(r[3]) : "r"(addr));
}
__device__ __forceinline__ void mma16816(float* c, const uint32_t* a, const uint32_t* b) {
    asm volatile(
        "mma.sync.aligned.m16n8k16.row.col.f32.f16.f16.f32 "
        "{%0,%1,%2,%3}, {%4,%5,%6,%7}, {%8,%9}, {%0,%1,%2,%3};"
        : "+f"(c[0]), "+f"(c[1]), "+f"(c[2]), "+f"(c[3])
        : "r"(a[0]), "r"(a[1]), "r"(a[2]), "r"(a[3]), "r"(b[0]), "r"(b[1]));
}
#define CP_ASYNC16(dst, src) \
    asm volatile("cp.async.cg.shared.global [%0], [%1], 16;" :: "r"(dst), "l"(src))
#define CP_COMMIT() asm volatile("cp.async.commit_group;" ::: "memory")
#define CP_WAIT1()  asm volatile("cp.async.wait_group 1;" ::: "memory")
#define CP_WAIT0()  asm volatile("cp.async.wait_group 0;" ::: "memory")

// ---------------------------------------------------------------------------
// Main GEMM: 128x128 tile, virtual K' = 2K (Ah*B, Al*B), BK=64 chunks,
// 3-stage cp.async ring, 8 warps (2x4), 2 CTAs/SM.
// ---------------------------------------------------------------------------
#define GSMEM (3*32768)

template<bool SOFTPLUS, bool OUTHL>
__global__ __launch_bounds__(256, 2)
void gemm_f16(const __half* __restrict__ A0, const __half* __restrict__ A1,
              const __half* __restrict__ B0, const __half* __restrict__ B1,
              float* C0, float* C1, int ldc,
              __half* Cb0, __half* Cb1, int ldcb, int koffb,
              int K, const float* bias0, const float* bias1,
              int flipa0, int flipa1, int flipc0, int flipc1)
{
    extern __shared__ __align__(128) char smem_raw[];
    const uint32_t sbase = (uint32_t)__cvta_generic_to_shared(smem_raw);

    const int z = blockIdx.z;
    const __half* A = z ? A1 : A0;
    const __half* B = z ? B1 : B0;
    float* C = z ? C1 : C0;
    __half* Cb = z ? Cb1 : Cb0;
    const float* bias = z ? bias1 : bias0;
    const int flipa = z ? flipa1 : flipa0;
    const int flipc = z ? flipc1 : flipc0;

    const int tid = threadIdx.x;
    const int wid = tid >> 5;
    const int lid = tid & 31;
    const int bm = blockIdx.y * 128;
    const int bn = blockIdx.x * 128;

    const int wm = wid >> 2;
    const int wn = wid & 3;
    const int mbase = wm * 64;
    const int nbase = wn * 32;

    const int qrow = lid & 15;
    const int qc16 = lid >> 4;

    const int lda2 = 2 * K;
    const int nk = K >> 6;
    const int nv = 2 * nk;

    float acc[4][4][4];
#pragma unroll
    for (int f = 0; f < 4; f++)
#pragma unroll
        for (int g = 0; g < 4; g++)
#pragma unroll
            for (int e = 0; e < 4; e++) acc[f][g][e] = 0.f;

    auto sA = [&](int st) -> uint32_t { return sbase + (uint32_t)st * 32768u; };
    auto sB = [&](int st) -> uint32_t { return sbase + (uint32_t)st * 32768u + 16384u; };

    auto load_stage = [&](int v, int st) {
        int aoff, boff;
        if (v < nk) { aoff = v << 6;               boff = v << 6; }
        else        { aoff = K + ((v - nk) << 6);  boff = (v - nk) << 6; }
        uint32_t da = sA(st), db = sB(st);
#pragma unroll
        for (int i = 0; i < 4; i++) {
            int ch  = tid + (i << 8);
            int r   = ch >> 3;
            int c16 = ch & 7;
            uint32_t sw = (uint32_t)((c16 ^ (r & 7)) << 4) + (uint32_t)(r << 7);
            int gm = bm + r;
            int am = flipa ? (gm ^ (SEQ-1)) : gm;
            CP_ASYNC16(da + sw, A + (size_t)am * lda2 + aoff + (c16 << 3));
            CP_ASYNC16(db + sw, B + (size_t)(bn + r) * K + boff + (c16 << 3));
        }
    };

    auto compute_stage = [&](int st) {
        uint32_t sa = sA(st), sb = sB(st);
#pragma unroll
        for (int s = 0; s < 4; s++) {
            uint32_t bq[2][4];
#pragma unroll
            for (int g2 = 0; g2 < 2; g2++) {
                int r = nbase + g2*16 + qrow;
                int c = (s << 1) + qc16;
                ldsm_x4(bq[g2], sb + (uint32_t)(r << 7) + (uint32_t)((c ^ (r & 7)) << 4));
            }
#pragma unroll
            for (int f = 0; f < 4; f++) {
                int r = mbase + f*16 + qrow;
                int c = (s << 1) + qc16;
                uint32_t afr[4];
                ldsm_x4(afr, sa + (uint32_t)(r << 7) + (uint32_t)((c ^ (r & 7)) << 4));
#pragma unroll
                for (int g = 0; g < 4; g++) {
                    uint32_t bfr[2] = { bq[g >> 1][g & 1], bq[g >> 1][(g & 1) + 2] };
                    mma16816(acc[f][g], afr, bfr);
                }
            }
        }
    };

    load_stage(0, 0); CP_COMMIT();
    if (nv > 1) { load_stage(1, 1); CP_COMMIT(); }

    for (int v = 0; v < nv; v++) {
        int st = v % 3;
        if (v < nv - 1) CP_WAIT1(); else CP_WAIT0();
        __syncthreads();
        compute_stage(st);
        int vn = v + 2;
        if (vn < nv) { load_stage(vn, vn % 3); CP_COMMIT(); }
    }

    // ---- epilogue ----
    const int crow = lid >> 2;
    const int ccol = (lid & 3) * 2;
#pragma unroll
    for (int f = 0; f < 4; f++) {
        int m0 = bm + mbase + f*16 + crow;
        int m1 = m0 + 8;
        int gm0 = flipc ? (m0 ^ (SEQ-1)) : m0;
        int gm1 = flipc ? (m1 ^ (SEQ-1)) : m1;
#pragma unroll
        for (int g = 0; g < 4; g++) {
            int n = bn + nbase + g*8 + ccol;
            float v0 = acc[f][g][0], v1 = acc[f][g][1];
            float v2 = acc[f][g][2], v3 = acc[f][g][3];
            if (SOFTPLUS) {
                float b0 = bias[n], b1 = bias[n+1];
                float x0 = v0 + b0, x1 = v1 + b1, x2 = v2 + b0, x3 = v3 + b1;
                v0 = (x0 > 20.f) ? x0 : log1pf(__expf(x0));
                v1 = (x1 > 20.f) ? x1 : log1pf(__expf(x1));
                v2 = (x2 > 20.f) ? x2 : log1pf(__expf(x2));
                v3 = (x3 > 20.f) ? x3 : log1pf(__expf(x3));
            }
            if (OUTHL) {
                __half h0 = __float2half_rn(v0), h1 = __float2half_rn(v1);
                __half h2 = __float2half_rn(v2), h3 = __float2half_rn(v3);
                __half l0 = __float2half_rn(v0 - __half2float(h0));
                __half l1 = __float2half_rn(v1 - __half2float(h1));
                __half l2 = __float2half_rn(v2 - __half2float(h2));
                __half l3 = __float2half_rn(v3 - __half2float(h3));
                *reinterpret_cast<__half2*>(Cb + (size_t)gm0*ldcb + n)         = __halves2half2(h0, h1);
                *reinterpret_cast<__half2*>(Cb + (size_t)gm0*ldcb + koffb + n) = __halves2half2(l0, l1);
                *reinterpret_cast<__half2*>(Cb + (size_t)gm1*ldcb + n)         = __halves2half2(h2, h3);
                *reinterpret_cast<__half2*>(Cb + (size_t)gm1*ldcb + koffb + n) = __halves2half2(l2, l3);
            } else {
                *reinterpret_cast<float2*>(C + (size_t)gm0*ldc + n) = make_float2(v0, v1);
                *reinterpret_cast<float2*>(C + (size_t)gm1*ldc + n) = make_float2(v2, v3);
            }
        }
    }
}

// ---------------------------------------------------------------------------
// fp32 -> [hi(K)|lo(K)] fp16 split (A-side operands)
// ---------------------------------------------------------------------------
__global__ void cvt_split(const float* __restrict__ in, __half* __restrict__ out, int K)
{
    int idx = (blockIdx.x * blockDim.x + threadIdx.x) << 2;
    int row = idx / K;
    int col = idx - row * K;
    float4 v = *reinterpret_cast<const float4*>(in + idx);
    __half h0 = __float2half_rn(v.x), h1 = __float2half_rn(v.y);
    __half h2 = __float2half_rn(v.z), h3 = __float2half_rn(v.w);
    __half l0 = __float2half_rn(v.x - __half2float(h0));
    __half l1 = __float2half_rn(v.y - __half2float(h1));
    __half l2 = __float2half_rn(v.z - __half2float(h2));
    __half l3 = __float2half_rn(v.w - __half2float(h3));
    size_t o = (size_t)row * 2 * K + col;
    *reinterpret_cast<__half2*>(out + o)         = __halves2half2(h0, h1);
    *reinterpret_cast<__half2*>(out + o + 2)     = __halves2half2(h2, h3);
    *reinterpret_cast<__half2*>(out + o + K)     = __halves2half2(l0, l1);
    *reinterpret_cast<__half2*>(out + o + K + 2) = __halves2half2(l2, l3);
}

// fp32 -> plain fp16 (B-side weights), flat
__global__ void cvt_w(const float* __restrict__ in, __half* __restrict__ out)
{
    int idx = (blockIdx.x * blockDim.x + threadIdx.x) << 2;
    float4 v = *reinterpret_cast<const float4*>(in + idx);
    __half2 a = __halves2half2(__float2half_rn(v.x), __float2half_rn(v.y));
    __half2 b = __halves2half2(__float2half_rn(v.z), __float2half_rn(v.w));
    *reinterpret_cast<__half2*>(out + idx)     = a;
    *reinterpret_cast<__half2*>(out + idx + 2) = b;
}

// dbl (stride 96, cols 0..63) -> packed 2048 x 128 fp16 hi/lo; both dirs
__global__ void cvt_dt(const float* __restrict__ in0, __half* __restrict__ out0,
                       const float* __restrict__ in1, __half* __restrict__ out1)
{
    const float* in = blockIdx.y ? in1 : in0;
    __half* out = blockIdx.y ? out1 : out0;
    int idx = (blockIdx.x * blockDim.x + threadIdx.x) << 2;
    int row = idx >> 6;
    int col = idx & 63;
    float4 v = *reinterpret_cast<const float4*>(in + (size_t)row * 96 + col);
    __half h0 = __float2half_rn(v.x), h1 = __float2half_rn(v.y);
    __half h2 = __float2half_rn(v.z), h3 = __float2half_rn(v.w);
    __half l0 = __float2half_rn(v.x - __half2float(h0));
    __half l1 = __float2half_rn(v.y - __half2float(h1));
    __half l2 = __float2half_rn(v.z - __half2float(h2));
    __half l3 = __float2half_rn(v.w - __half2float(h3));
    size_t o = (size_t)row * 128 + col;
    *reinterpret_cast<__half2*>(out + o)          = __halves2half2(h0, h1);
    *reinterpret_cast<__half2*>(out + o + 2)      = __halves2half2(h2, h3);
    *reinterpret_cast<__half2*>(out + o + 64)     = __halves2half2(l0, l1);
    *reinterpret_cast<__half2*>(out + o + 64 + 2) = __halves2half2(l2, l3);
}

// ---------------------------------------------------------------------------
// Small split-K fp32 GEMM with atomicAdd epilogue (x_proj), both dirs (grid.z)
// ---------------------------------------------------------------------------
template<int BM,int BN,int BK,int TM,int TN>
__global__ __launch_bounds__((BM/TM)*(BN/TN))
void gemm_nt_atomic(const float* __restrict__ A0, const float* __restrict__ B0, float* C0,
                    const float* __restrict__ A1, const float* __restrict__ B1, float* C1,
                    int lda, int ldb, int ldc, int kslab)
{
    constexpr int THREADS = (BM/TM)*(BN/TN);
    __shared__ float As[BK][BM];
    __shared__ float Bs[BK][BN];
    const float* A = blockIdx.z ? A1 : A0;
    const float* B = blockIdx.z ? B1 : B0;
    float* C = blockIdx.z ? C1 : C0;
    const int tid = threadIdx.x;
    const int bm  = blockIdx.y * BM;
    const int k_lo = blockIdx.x * kslab;
    const int tx = tid % (BN/TN);
    const int ty = tid / (BN/TN);

    float acc[TM][TN];
#pragma unroll
    for (int i = 0; i < TM; i++)
#pragma unroll
        for (int j = 0; j < TN; j++) acc[i][j] = 0.f;

    constexpr int A4 = BM*BK/4;
    constexpr int B4 = BN*BK/4;
    for (int k0 = k_lo; k0 < k_lo + kslab; k0 += BK) {
        for (int i = tid; i < A4; i += THREADS) {
            int r  = i / (BK/4);
            int kq = (i % (BK/4)) * 4;
            float4 v = *reinterpret_cast<const float4*>(A + (size_t)(bm+r)*lda + k0 + kq);
            As[kq+0][r] = v.x; As[kq+1][r] = v.y; As[kq+2][r] = v.z; As[kq+3][r] = v.w;
        }
        for (int i = tid; i < B4; i += THREADS) {
            int r  = i / (BK/4);
            int kq = (i % (BK/4)) * 4;
            float4 v = *reinterpret_cast<const float4*>(B + (size_t)r*ldb + k0 + kq);
            Bs[kq+0][r] = v.x; Bs[kq+1][r] = v.y; Bs[kq+2][r] = v.z; Bs[kq+3][r] = v.w;
        }
        __syncthreads();
#pragma unroll
        for (int k = 0; k < BK; k++) {
            float a[TM], b[TN];
#pragma unroll
            for (int i = 0; i < TM; i++) a[i] = As[k][ty*TM + i];
#pragma unroll
            for (int j = 0; j < TN; j++) b[j] = Bs[k][tx*TN + j];
#pragma unroll
            for (int i = 0; i < TM; i++)
#pragma unroll
                for (int j = 0; j < TN; j++)
                    acc[i][j] = fmaf(a[i], b[j], acc[i][j]);
        }
        __syncthreads();
    }
#pragma unroll
    for (int i = 0; i < TM; i++)
#pragma unroll
        for (int j = 0; j < TN; j++)
            atomicAdd(&C[(size_t)(bm + ty*TM + i)*ldc + tx*TN + j], acc[i][j]);
}

// ---------------------------------------------------------------------------
// Depthwise causal conv1d (k=4) + SiLU
// ---------------------------------------------------------------------------
__global__ void conv_silu_kernel(const float* __restrict__ cw_f, const float* __restrict__ cb_f,
                                 const float* __restrict__ cw_b, const float* __restrict__ cb_b)
{
    const int dir = blockIdx.y;
    const float* xz = g_xz[dir];
    const float* cw = dir ? cw_b : cw_f;
    const float* cb = dir ? cb_b : cb_f;
    float* xc = g_xc[dir];

    int idx = blockIdx.x * blockDim.x + threadIdx.x;
    int e = idx & (DINNER-1);
    int t = idx >> 11;
    int l = t & (SEQ-1);
    int base = t - l;

    float acc = cb[e];
#pragma unroll
    for (int k = 0; k < 4; k++) {
        int ls = l + k - 3;
        if (ls >= 0)
            acc = fmaf(cw[e*4 + k], xz[(size_t)(base + ls)*(2*DINNER) + e], acc);
    }
    acc = acc / (1.f + __expf(-acc));
    xc[idx] = acc;
}

// ---------------------------------------------------------------------------
// Selective scan + skip + gate; dA via r^k powers (A[n] = -(n+1) fast path).
// Writes y as fp16 hi/lo.
// ---------------------------------------------------------------------------
__global__ void scan_kernel(const float* __restrict__ Alog_f, const float* __restrict__ D_f,
                            const float* __restrict__ Alog_b, const float* __restrict__ D_b)
{
    const int dir = blockIdx.z;
    const int b   = blockIdx.y;
    const int e   = blockIdx.x * blockDim.x + threadIdx.x;

    const float* delta = g_delta[dir];
    const float* xc    = g_xc[dir];
    const float* dbl   = g_dbl[dir];
    const float* xz    = g_xz[dir];
    __half* yhl        = g_yhl[dir];
    const float* Alog  = dir ? Alog_b : Alog_f;
    const float* Dp    = dir ? D_b    : D_f;

    float A[DSTATE], h[DSTATE];
    bool fast = true;
#pragma unroll
    for (int n = 0; n < DSTATE; n++) {
        A[n] = -expf(Alog[e*DSTATE + n]);
        h[n] = 0.f;
        fast = fast && (fabsf(A[n] + (float)(n+1)) < 1e-3f * (float)(n+1));
    }
    const float Dv = Dp[e];

    for (int l = 0; l < SEQ; l++) {
        const int t = b*SEQ + l;
        const float dlt = delta[(size_t)t*DINNER + e];
        const float xcv = xc[(size_t)t*DINNER + e];
        const float du  = dlt * xcv;
        const float* row = dbl + (size_t)t*96;

        float dA[DSTATE];
        if (fast) {
            const float r  = __expf(-dlt);
            const float r2 = r*r, r4 = r2*r2, r8 = r4*r4;
            dA[0]=r;        dA[1]=r2;       dA[2]=r2*r;     dA[3]=r4;
            dA[4]=r4*r;     dA[5]=r4*r2;    dA[6]=r4*dA[2]; dA[7]=r8;
            dA[8]=r8*r;     dA[9]=r8*r2;    dA[10]=r8*dA[2];dA[11]=r8*r4;
            dA[12]=r8*dA[4];dA[13]=r8*dA[5];dA[14]=r8*dA[6];dA[15]=r8*r8;
        } else {
#pragma unroll
            for (int n = 0; n < DSTATE; n++) dA[n] = __expf(dlt * A[n]);
        }

        float y0 = 0.f, y1 = 0.f, y2 = 0.f, y3 = 0.f;
#pragma unroll
        for (int n = 0; n < DSTATE; n += 4) {
            h[n+0] = fmaf(dA[n+0], h[n+0], du * row[64+n+0]);
            h[n+1] = fmaf(dA[n+1], h[n+1], du * row[64+n+1]);
            h[n+2] = fmaf(dA[n+2], h[n+2], du * row[64+n+2]);
            h[n+3] = fmaf(dA[n+3], h[n+3], du * row[64+n+3]);
            y0 = fmaf(h[n+0], row[80+n+0], y0);
            y1 = fmaf(h[n+1], row[80+n+1], y1);
            y2 = fmaf(h[n+2], row[80+n+2], y2);
            y3 = fmaf(h[n+3], row[80+n+3], y3);
        }
        float y = (y0 + y1) + (y2 + y3);

        const float zv = xz[(size_t)t*(2*DINNER) + DINNER + e];
        const float g  = zv / (1.f + __expf(-zv));
        float yv = (y + xcv*Dv) * g;

        __half hh = __float2half_rn(yv);
        __half ll = __float2half_rn(yv - __half2float(hh));
        yhl[(size_t)t*(2*DINNER) + e]          = hh;
        yhl[(size_t)t*(2*DINNER) + DINNER + e] = ll;
    }
}

// ---------------------------------------------------------------------------
extern "C" void kernel_launch(void* const* d_in, const int* in_sizes, int n_in,
                              void* d_out, int out_size)
{
    const float* x       = (const float*)d_in[0];
    const float* f_inp   = (const float*)d_in[1];
    const float* f_cw    = (const float*)d_in[2];
    const float* f_cb    = (const float*)d_in[3];
    const float* f_xp    = (const float*)d_in[4];
    const float* f_dtw   = (const float*)d_in[5];
    const float* f_dtb   = (const float*)d_in[6];
    const float* f_Alog  = (const float*)d_in[7];
    const float* f_D     = (const float*)d_in[8];
    const float* f_op    = (const float*)d_in[9];
    const float* b_inp   = (const float*)d_in[10];
    const float* b_cw    = (const float*)d_in[11];
    const float* b_cb    = (const float*)d_in[12];
    const float* b_xp    = (const float*)d_in[13];
    const float* b_dtw   = (const float*)d_in[14];
    const float* b_dtb   = (const float*)d_in[15];
    const float* b_Alog  = (const float*)d_in[16];
    const float* b_D     = (const float*)d_in[17];
    const float* b_op    = (const float*)d_in[18];
    const float* merge_w = (const float*)d_in[19];
    float* out = (float*)d_out;

    void* p;
    cudaGetSymbolAddress(&p, g_xz);    float* xz0 = (float*)p; float* xz1 = xz0 + PLANE_XZ;
    cudaGetSymbolAddress(&p, g_dbl);   float* db0 = (float*)p; float* db1 = db0 + PLANE_DBL;
    cudaGetSymbolAddress(&p, g_delta); float* dl0 = (float*)p; float* dl1 = dl0 + PLANE_E;
    cudaGetSymbolAddress(&p, g_xc);    float* xc0 = (float*)p; float* xc1 = xc0 + PLANE_E;

    __half *xhl, *win0, *win1, *wdt0, *wdt1, *wop0, *wop1, *wmg,
           *dth0, *dth1, *yh0, *yh1, *ocat;
    cudaGetSymbolAddress(&p, g_xhl);  xhl  = (__half*)p;
    cudaGetSymbolAddress(&p, g_win);  win0 = (__half*)p; win1 = win0 + (size_t)2*DINNER*DMODEL;
    cudaGetSymbolAddress(&p, g_wdt);  wdt0 = (__half*)p; wdt1 = wdt0 + (size_t)DINNER*DTRANK;
    cudaGetSymbolAddress(&p, g_wop);  wop0 = (__half*)p; wop1 = wop0 + (size_t)DMODEL*DINNER;
    cudaGetSymbolAddress(&p, g_wmg);  wmg  = (__half*)p;
    cudaGetSymbolAddress(&p, g_dthl); dth0 = (__half*)p; dth1 = dth0 + (size_t)TOK*2*DTRANK;
    cudaGetSymbolAddress(&p, g_yhl);  yh0  = (__half*)p; yh1  = yh0  + (size_t)TOK*2*DINNER;
    cudaGetSymbolAddress(&p, g_ocat); ocat = (__half*)p;

    cudaFuncSetAttribute((const void*)gemm_f16<false,false>, cudaFuncAttributeMaxDynamicSharedMemorySize, GSMEM);
    cudaFuncSetAttribute((const void*)gemm_f16<true ,false>, cudaFuncAttributeMaxDynamicSharedMemorySize, GSMEM);
    cudaFuncSetAttribute((const void*)gemm_f16<false,true >, cudaFuncAttributeMaxDynamicSharedMemorySize, GSMEM);

    // Exactly 5 launches before the big GEMM (memset counts!), so ncu's
    // "-s 5 -c 1" profiles the in_proj GEMM.
    cudaMemsetAsync(db0, 0, 2 * PLANE_DBL * sizeof(float));                      // 1
    cvt_split<<<(TOK*DMODEL)/1024, 256>>>(x, xhl, DMODEL);                       // 2
    cvt_w<<<((size_t)2*DINNER*DMODEL)/1024, 256>>>(f_inp, win0);                 // 3
    cvt_w<<<((size_t)2*DINNER*DMODEL)/1024, 256>>>(b_inp, win1);                 // 4
    cvt_w<<<((size_t)DINNER*DTRANK)/1024, 256>>>(f_dtw, wdt0);                   // 5

    // 6) in_proj both dirs: xz = X @ in_proj^T  (M=2048, N=4096, K=1024)
    {
        dim3 grid(4096/128, TOK/128, 2);
        gemm_f16<false,false><<<grid,256,GSMEM>>>(
            xhl, xhl, win0, win1, xz0, xz1, 2*DINNER,
            nullptr, nullptr, 0, 0, DMODEL, nullptr, nullptr,
            /*flipa*/0, 1, /*flipc*/0, 0);
    }

    // remaining weight converts
    cvt_w<<<((size_t)DINNER*DTRANK)/1024, 256>>>(b_dtw, wdt1);
    cvt_w<<<((size_t)DMODEL*DINNER)/1024, 256>>>(f_op, wop0);
    cvt_w<<<((size_t)DMODEL*DINNER)/1024, 256>>>(b_op, wop1);
    cvt_w<<<((size_t)DMODEL*2*DMODEL)/1024, 256>>>(merge_w, wmg);

    // depthwise conv + SiLU (both dirs)
    {
        dim3 grid((TOK*DINNER)/256, 2);
        conv_silu_kernel<<<grid,256>>>(f_cw, f_cb, b_cw, b_cb);
    }

    // x_proj both dirs: dbl = xc @ x_proj^T  (M=2048, N=96, K=2048), split-K=8
    {
        dim3 grid(8, TOK/32, 2);
        gemm_nt_atomic<32,96,16,2,6><<<grid,256>>>(
            xc0, f_xp, db0, xc1, b_xp, db1, DINNER, DINNER, 96, DINNER/8);
    }

    // split dt columns of dbl (both dirs)
    {
        dim3 grid((TOK*DTRANK)/1024, 2);
        cvt_dt<<<grid, 256>>>(db0, dth0, db1, dth1);
    }

    // dt projection + fused bias/softplus, both dirs (M=2048, N=2048, K=64)
    {
        dim3 grid(DINNER/128, TOK/128, 2);
        gemm_f16<true,false><<<grid,256,GSMEM>>>(
            dth0, dth1, wdt0, wdt1, dl0, dl1, DINNER,
            nullptr, nullptr, 0, 0, DTRANK, f_dtb, b_dtb, 0, 0, 0, 0);
    }

    // selective scan + skip + gate -> yhl (fp16 hi/lo)
    {
        dim3 grid(DINNER/128, BSZ, 2);
        scan_kernel<<<grid,128>>>(f_Alog, f_D, b_Alog, b_D);
    }

    // out_proj both dirs (M=2048, N=1024, K=2048) -> ocat hi/lo, bwd flipped
    {
        dim3 grid(DMODEL/128, TOK/128, 2);
        gemm_f16<false,true><<<grid,256,GSMEM>>>(
            yh0, yh1, wop0, wop1, nullptr, nullptr, 0,
            ocat, ocat + DMODEL, 2*(2*DMODEL), 2*DMODEL, DINNER,
            nullptr, nullptr, 0, 0, /*flipc*/0, 1);
    }

    // merge: out = [f | flip(b)] @ merge_w^T  (M=2048, N=1024, K=2048)
    {
        dim3 grid(DMODEL/128, TOK/128, 1);
        gemm_f16<false,false><<<grid,256,GSMEM>>>(
            ocat, ocat, wmg, wmg, out, out, DMODEL,
            nullptr, nullptr, 0, 0, 2*DMODEL, nullptr, nullptr, 0, 0, 0, 0);
    }
}